// round 8
// baseline (speedup 1.0000x reference)
#include <cuda_runtime.h>

#define NC    6
#define CF    64
#define Hh    88
#define Ww    160
#define HWp   (Hh*Ww)          // 14080
#define XD    100
#define YD    100
#define ZD    20
#define NVOX  (XD*YD*ZD)       // 200000

// scratch
__device__ float  g_featT[NC * HWp * CF];     // channel-last features [cam][H][W][C]
__device__ float4 g_q1[NVOX * 2];             // count==1 records
__device__ float4 g_q2[NVOX * 2];             // count==2 records
__device__ int    g_cnt[2];
__device__ float  g_f1[(size_t)(NVOX + 64) * 68];   // staged feats q1: [idx][68]
__device__ float  g_f2[(size_t)(NVOX + 64) * 132];  // staged feats q2: [idx][132]

__device__ __forceinline__ float elu1(float x) { return x > 0.f ? x : expm1f(x); }

__global__ void init_kernel() {
    if (threadIdx.x < 2) g_cnt[threadIdx.x] = 0;
}

__global__ void transpose_kernel(const float* __restrict__ feat) {
    __shared__ float tile[32][33];
    int cam = blockIdx.z;
    int c0  = blockIdx.y * 32;
    int p0  = blockIdx.x * 32;
    int tx = threadIdx.x, ty = threadIdx.y;
    const float* src = feat + (size_t)cam * CF * HWp;
#pragma unroll
    for (int i = ty; i < 32; i += 8)
        tile[i][tx] = src[(c0 + i) * HWp + p0 + tx];
    __syncthreads();
    float* dst = g_featT + (size_t)cam * HWp * CF;
#pragma unroll
    for (int i = ty; i < 32; i += 8)
        dst[(p0 + i) * CF + c0 + tx] = tile[tx][i];
}

__global__ __launch_bounds__(256) void classify_kernel(
    const float* __restrict__ mask,
    const float* __restrict__ Kin,
    const float* __restrict__ Ein,
    float* __restrict__ out)
{
    __shared__ float sE[96], sK[96];
    __shared__ int sh_cnt[2], sh_base[2];
    int tid = threadIdx.x;
    if (tid < 96) { sE[tid] = Ein[tid]; sK[tid] = Kin[tid]; }
    if (tid < 2) sh_cnt[tid] = 0;
    __syncthreads();

    int n = blockIdx.x * 256 + tid;
    int count = 0, camA = 0, camB = 0;
    float xsA = 0.f, ysA = 0.f, xsB = 0.f, ysB = 0.f, z0 = 0.f, z1 = 0.f;
    if (n < NVOX) {
        int x = n % XD, y = (n / XD) % YD, z = n / (XD * YD);
        float X = -50.f + (float)x;
        float Y = -50.f + (float)y;
        float Z = -15.f + 1.5f * (float)z;
#pragma unroll
        for (int cam = 0; cam < NC; cam++) {
            const float* E  = sE + cam * 16;
            const float* Km = sK + cam * 16;
            float vx = E[0] * X + E[1] * Y + E[2]  * Z + E[3];
            float vy = E[4] * X + E[5] * Y + E[6]  * Z + E[7];
            float vz = E[8] * X + E[9] * Y + E[10] * Z + E[11];
            if (!(vz > 0.f)) continue;
            float cx = Km[0] * vx + Km[1] * vy + Km[2]  * vz;
            float cy = Km[4] * vx + Km[5] * vy + Km[6]  * vz;
            float cz = Km[8] * vx + Km[9] * vy + Km[10] * vz;
            float denom = cz + 1e-8f;
            // ---- fast reject (safe margin >= 1 pixel; NaN/inf fall through) ----
            float rcp = __frcp_rn(denom);
            float pxa = cx * rcp, pya = cy * rcp;
            if (pxa < -1.f || pxa > 160.f || pya < -1.f || pya > 88.f) continue;
            // ---- exact path (bit-identical to reference) ----
            float px = __fdiv_rn(cx, denom);
            float py = __fdiv_rn(cy, denom);
            float gx = (__fdiv_rn(px, 159.f) - 0.5f) * 2.f;
            float gy = (__fdiv_rn(py,  87.f) - 0.5f) * 2.f;
            if (gx > 1.f || gx < -1.f || gy > 1.f || gy < -1.f) continue;
            float xs = (gx + 1.f) * 0.5f * 159.f;
            float ys = (gy + 1.f) * 0.5f * 87.f;
            float xr = rintf(xs), yr = rintf(ys);
            if (!(xr >= 0.f && xr <= 159.f && yr >= 0.f && yr <= 87.f)) continue;
            float mv = __ldg(mask + cam * HWp + (int)yr * Ww + (int)xr);
            if (!(mv > 0.5f)) continue;
            if (count == 0)      { camA = cam; xsA = xs; ysA = ys; }
            else if (count == 1) { camB = cam; xsB = xs; ysB = ys; }
            count++;
            float dz = __fdiv_rn(vz, 100.f);
            if (cam == 0 || cam == 3 || cam == 4) z0 += dz; else z1 += dz;
        }
    }
    int lane = tid & 31;
    unsigned lt = (1u << lane) - 1u;
    unsigned m1 = __ballot_sync(0xFFFFFFFFu, count == 1);
    unsigned m2 = __ballot_sync(0xFFFFFFFFu, count == 2);
    int w1 = 0, w2o = 0;
    if (m1) {
        int ldr = __ffs(m1) - 1;
        if (lane == ldr) w1 = atomicAdd(&sh_cnt[0], __popc(m1));
        w1 = __shfl_sync(0xFFFFFFFFu, w1, ldr);
    }
    if (m2) {
        int ldr = __ffs(m2) - 1;
        if (lane == ldr) w2o = atomicAdd(&sh_cnt[1], __popc(m2));
        w2o = __shfl_sync(0xFFFFFFFFu, w2o, ldr);
    }
    __syncthreads();
    if (tid < 2) sh_base[tid] = atomicAdd(&g_cnt[tid], sh_cnt[tid]);
    __syncthreads();
    if (n < NVOX) {
        if (count == 1) {
            int idx = sh_base[0] + w1 + __popc(m1 & lt);
            g_q1[idx * 2]     = make_float4(__int_as_float(n), __int_as_float(camA), xsA, ysA);
            g_q1[idx * 2 + 1] = make_float4(z0 + z1, 0.f, 0.f, 0.f);
        } else if (count == 2) {
            int idx = sh_base[1] + w2o + __popc(m2 & lt);
            g_q2[idx * 2]     = make_float4(__int_as_float(n), __int_as_float(camA | (camB << 8)), xsA, ysA);
            g_q2[idx * 2 + 1] = make_float4(xsB, ysB, z0, z1);
        } else {
            // inactive voxel: zero-fill its output column (replaces global memset)
#pragma unroll
            for (int o = 0; o < 64; o++) out[(size_t)o * NVOX + n] = 0.f;
        }
    }
}

__device__ __forceinline__ float2 bilin(int cam, float xs, float ys, int lane) {
    float x0 = floorf(xs), y0 = floorf(ys);
    float wx1 = xs - x0, wx0 = 1.f - wx1;
    float wy1 = ys - y0, wy0 = 1.f - wy1;
    float ax = 0.f, ay = 0.f;
    const float2* base = (const float2*)(g_featT + (size_t)cam * HWp * CF);
#pragma unroll
    for (int corner = 0; corner < 4; corner++) {
        float xi = x0 + (float)(corner & 1);
        float yi = y0 + (float)(corner >> 1);
        if (xi >= 0.f && xi <= 159.f && yi >= 0.f && yi <= 87.f) {
            float w = ((corner & 1) ? wx1 : wx0) * ((corner >> 1) ? wy1 : wy0);
            int pixi = (int)yi * Ww + (int)xi;
            float2 v = __ldg(base + pixi * 32 + lane);
            ax += w * v.x;
            ay += w * v.y;
        }
    }
    return make_float2(ax, ay);
}

// gather: one warp per queue entry; writes dense staged feature rows.
// q1 row [68]:  [0..63]=channels, [64]=z, [65..67]=0
// q2 row [132]: [0..63]=g0 ch, [64..127]=g1 ch, [128]=z0, [129]=z1, [130,131]=0
__global__ __launch_bounds__(256) void gather_kernel() {
    int c1 = g_cnt[0], c2 = g_cnt[1];
    int total = c1 + c2;
    int lane = threadIdx.x & 31;
    int gw = blockIdx.x * 8 + (threadIdx.x >> 5);
    int nw = gridDim.x * 8;
    for (int w = gw; w < total; w += nw) {
        if (w < c1) {
            float4 ra = __ldg(g_q1 + w * 2);
            float4 rb = __ldg(g_q1 + w * 2 + 1);
            int cam = __float_as_int(ra.y);
            float2 a = bilin(cam, ra.z, ra.w, lane);
            float* dst = g_f1 + (size_t)w * 68;
            *(float2*)(dst + 2 * lane) = a;
            if (lane == 0) *(float4*)(dst + 64) = make_float4(rb.x, 0.f, 0.f, 0.f);
        } else {
            int idx = w - c1;
            float4 ra = __ldg(g_q2 + idx * 2);
            float4 rb = __ldg(g_q2 + idx * 2 + 1);
            int cc = __float_as_int(ra.y);
            int camA = cc & 255, camB = cc >> 8;
            float2 a = bilin(camA, ra.z, ra.w, lane);
            float2 b = bilin(camB, rb.x, rb.y, lane);
            float2 h0 = make_float2(0.f, 0.f), h1 = make_float2(0.f, 0.f);
            if (camA == 0 || camA == 3 || camA == 4) { h0.x += a.x; h0.y += a.y; }
            else                                     { h1.x += a.x; h1.y += a.y; }
            if (camB == 0 || camB == 3 || camB == 4) { h0.x += b.x; h0.y += b.y; }
            else                                     { h1.x += b.x; h1.y += b.y; }
            float* dst = g_f2 + (size_t)idx * 132;
            *(float2*)(dst + 2 * lane)      = h0;
            *(float2*)(dst + 64 + 2 * lane) = h1;
            if (lane == 0) *(float4*)(dst + 128) = make_float4(rb.z, rb.w, 0.f, 0.f);
        }
    }
}

// streaming GEMM: 64 outputs x 64 voxels per tile; weights in smem,
// feats via warp-broadcast LDG.128 from staging (no smem feats, no gather chain).
template<int KP, int QIDX>
__global__ __launch_bounds__(256, 4) void gemm_kernel(
    const float* __restrict__ W,      // [64, KR] row-major original
    const float* __restrict__ bias,   // [64]
    float* __restrict__ out)          // [64, NVOX]
{
    extern __shared__ float smem[];
    float2* w2  = (float2*)smem;                 // [KP][32] : {W[l][col(k)], W[l+32][col(k)]}
    float*  som = smem + KP * 64;                // [64][65] output staging
    float*  sb  = som + 64 * 65;                 // [64]
    int*    s_n = (int*)(sb + 64);               // [64]

    int total = g_cnt[QIDX];
    if (blockIdx.x * 64 >= total) return;        // early exit BEFORE weight load

    int tid = threadIdx.x, lane = tid & 31, warp = tid >> 5;
    const int KR = QIDX ? 130 : 65;
    for (int i = tid; i < KP * 32; i += 256) {
        int k = i >> 5, l = i & 31;
        int col;
        if (QIDX == 0) col = (k < 65) ? k : -1;
        else col = (k < 64) ? k : (k < 128 ? k + 1 : (k == 128 ? 64 : (k == 129 ? 129 : -1)));
        float2 v = make_float2(0.f, 0.f);
        if (col >= 0) v = make_float2(W[l * KR + col], W[(l + 32) * KR + col]);
        w2[i] = v;
    }
    if (tid < 64) sb[tid] = bias[tid];

    const float4* q = QIDX ? g_q2 : g_q1;
    const float*  F = QIDX ? g_f2 : g_f1;
    for (int tile = blockIdx.x; tile * 64 < total; tile += gridDim.x) {
        __syncthreads();   // weights ready / previous write-out done with som & s_n
        if (tid < 64) {
            int r = tile * 64 + tid;
            s_n[tid] = (r < total) ? __float_as_int(__ldg(q + r * 2).x) : -1;
        }
        // ---- GEMM: warp -> voxels [warp*8, warp*8+8), thread -> outputs (lane, lane+32) ----
        int vb = warp * 8;
        const float* fb = F + (size_t)(tile * 64 + vb) * KP;
        float acc[16];
#pragma unroll
        for (int i = 0; i < 16; i++) acc[i] = 0.f;
#pragma unroll 4
        for (int k = 0; k < KP; k += 4) {
            float2 w0 = w2[(k + 0) * 32 + lane];
            float2 w1 = w2[(k + 1) * 32 + lane];
            float2 w2v = w2[(k + 2) * 32 + lane];
            float2 w3 = w2[(k + 3) * 32 + lane];
#pragma unroll
            for (int j = 0; j < 8; j++) {
                float4 f = *(const float4*)(fb + (size_t)j * KP + k);   // warp-broadcast
                acc[2*j]   = fmaf(w0.x, f.x, acc[2*j]);
                acc[2*j+1] = fmaf(w0.y, f.x, acc[2*j+1]);
                acc[2*j]   = fmaf(w1.x, f.y, acc[2*j]);
                acc[2*j+1] = fmaf(w1.y, f.y, acc[2*j+1]);
                acc[2*j]   = fmaf(w2v.x, f.z, acc[2*j]);
                acc[2*j+1] = fmaf(w2v.y, f.z, acc[2*j+1]);
                acc[2*j]   = fmaf(w3.x, f.w, acc[2*j]);
                acc[2*j+1] = fmaf(w3.y, f.w, acc[2*j+1]);
            }
        }
        float b0 = sb[lane], b1 = sb[lane + 32];
#pragma unroll
        for (int j = 0; j < 8; j++) {
            som[lane * 65 + vb + j]        = elu1(acc[2 * j]     + b0);
            som[(lane + 32) * 65 + vb + j] = elu1(acc[2 * j + 1] + b1);
        }
        __syncthreads();
        // ---- write-out: row-major, near-coalesced over clustered queue columns ----
#pragma unroll
        for (int i = tid; i < 64 * 64; i += 256) {
            int o = i >> 6, v = i & 63;
            int nn = s_n[v];
            if (nn >= 0) out[(size_t)o * NVOX + nn] = som[o * 65 + v];
        }
    }
}

extern "C" void kernel_launch(void* const* d_in, const int* in_sizes, int n_in,
                              void* d_out, int out_size) {
    const float* feat = (const float*)d_in[0];
    const float* mask = (const float*)d_in[1];
    const float* K    = (const float*)d_in[2];
    const float* ext  = (const float*)d_in[3];
    const float* w_no = (const float*)d_in[4];
    const float* b_no = (const float*)d_in[5];
    const float* w_o  = (const float*)d_in[6];
    const float* b_o  = (const float*)d_in[7];
    float* out = (float*)d_out;

    static cudaStream_t s1 = nullptr;
    static cudaEvent_t e0 = nullptr, e_t = nullptr, e_g = nullptr, e_g2 = nullptr;
    if (!s1) {
        cudaStreamCreateWithFlags(&s1, cudaStreamNonBlocking);
        cudaEventCreateWithFlags(&e0,  cudaEventDisableTiming);
        cudaEventCreateWithFlags(&e_t, cudaEventDisableTiming);
        cudaEventCreateWithFlags(&e_g, cudaEventDisableTiming);
        cudaEventCreateWithFlags(&e_g2, cudaEventDisableTiming);
    }

    const int smem1 = (68 * 64  + 64 * 65 + 64) * 4 + 256;   // ~34.3KB
    const int smem2 = (132 * 64 + 64 * 65 + 64) * 4 + 256;   // ~50.7KB
    cudaFuncSetAttribute(gemm_kernel<68, 0>,  cudaFuncAttributeMaxDynamicSharedMemorySize, smem1);
    cudaFuncSetAttribute(gemm_kernel<132, 1>, cudaFuncAttributeMaxDynamicSharedMemorySize, smem2);

    // fork: transpose on s1; init+classify on capture stream (concurrent)
    cudaEventRecord(e0, 0);
    cudaStreamWaitEvent(s1, e0, 0);

    dim3 tg(HWp / 32, CF / 32, NC);   // 440 x 2 x 6
    transpose_kernel<<<tg, dim3(32, 8), 0, s1>>>(feat);
    cudaEventRecord(e_t, s1);

    init_kernel<<<1, 32>>>();
    classify_kernel<<<(NVOX + 255) / 256, 256>>>(mask, K, ext, out);

    // gather needs classify (program order) + transpose (event)
    cudaStreamWaitEvent(0, e_t, 0);
    gather_kernel<<<256, 256>>>();
    cudaEventRecord(e_g, 0);

    // fork the two GEMMs
    cudaStreamWaitEvent(s1, e_g, 0);
    gemm_kernel<68, 0><<<304, 256, smem1, 0>>>(w_no, b_no, out);
    gemm_kernel<132, 1><<<304, 256, smem2, s1>>>(w_o, b_o, out);
    cudaEventRecord(e_g2, s1);
    cudaStreamWaitEvent(0, e_g2, 0);
}

// round 10
// speedup vs baseline: 1.4693x; 1.4693x over previous
#include <cuda_runtime.h>

#define NC    6
#define CF    64
#define Hh    88
#define Ww    160
#define HWp   (Hh*Ww)          // 14080
#define XD    100
#define YD    100
#define ZD    20
#define NVOX  (XD*YD*ZD)       // 200000

// scratch
__device__ float  g_featT[NC * HWp * CF];   // channel-last features [cam][H][W][C]
__device__ float4 g_q1[NVOX * 2];           // count==1 records
__device__ float4 g_q2[NVOX * 2];           // count==2 records
__device__ int    g_cnt[2];
__device__ float2 g_w1p[65 * 32];           // packed w_no: [k][lane]={W[l][k],W[l+32][k]}
__device__ float2 g_w2p[130 * 32];          // packed w_o

__device__ __forceinline__ float elu1(float x) { return x > 0.f ? x : expm1f(x); }

__global__ void init_kernel() {
    if (threadIdx.x < 2) g_cnt[threadIdx.x] = 0;
}

__global__ void pack_kernel(const float* __restrict__ w_no, const float* __restrict__ w_o) {
    int i = blockIdx.x * 256 + threadIdx.x;
    if (i < 65 * 32) {
        int k = i >> 5, l = i & 31;
        g_w1p[i] = make_float2(w_no[l * 65 + k], w_no[(l + 32) * 65 + k]);
    }
    if (i < 130 * 32) {
        int k = i >> 5, l = i & 31;
        g_w2p[i] = make_float2(w_o[l * 130 + k], w_o[(l + 32) * 130 + k]);
    }
}

__global__ void transpose_kernel(const float* __restrict__ feat) {
    __shared__ float tile[32][33];
    int cam = blockIdx.z;
    int c0  = blockIdx.y * 32;
    int p0  = blockIdx.x * 32;
    int tx = threadIdx.x, ty = threadIdx.y;
    const float* src = feat + (size_t)cam * CF * HWp;
#pragma unroll
    for (int i = ty; i < 32; i += 8)
        tile[i][tx] = src[(c0 + i) * HWp + p0 + tx];
    __syncthreads();
    float* dst = g_featT + (size_t)cam * HWp * CF;
#pragma unroll
    for (int i = ty; i < 32; i += 8)
        dst[(p0 + i) * CF + c0 + tx] = tile[tx][i];
}

__global__ __launch_bounds__(256) void classify_kernel(
    const float* __restrict__ mask,
    const float* __restrict__ Kin,
    const float* __restrict__ Ein,
    float* __restrict__ out)
{
    __shared__ float sE[96], sK[96];
    __shared__ int sh_cnt[2], sh_base[2];
    int tid = threadIdx.x;
    if (tid < 96) { sE[tid] = Ein[tid]; sK[tid] = Kin[tid]; }
    if (tid < 2) sh_cnt[tid] = 0;
    __syncthreads();

    int n = blockIdx.x * 256 + tid;
    int count = 0, camA = 0, camB = 0;
    float xsA = 0.f, ysA = 0.f, xsB = 0.f, ysB = 0.f, z0 = 0.f, z1 = 0.f;
    if (n < NVOX) {
        int x = n % XD, y = (n / XD) % YD, z = n / (XD * YD);
        float X = -50.f + (float)x;
        float Y = -50.f + (float)y;
        float Z = -15.f + 1.5f * (float)z;
#pragma unroll
        for (int cam = 0; cam < NC; cam++) {
            const float* E  = sE + cam * 16;
            const float* Km = sK + cam * 16;
            float vx = E[0] * X + E[1] * Y + E[2]  * Z + E[3];
            float vy = E[4] * X + E[5] * Y + E[6]  * Z + E[7];
            float vz = E[8] * X + E[9] * Y + E[10] * Z + E[11];
            if (!(vz > 0.f)) continue;
            float cx = Km[0] * vx + Km[1] * vy + Km[2]  * vz;
            float cy = Km[4] * vx + Km[5] * vy + Km[6]  * vz;
            float cz = Km[8] * vx + Km[9] * vy + Km[10] * vz;
            float denom = cz + 1e-8f;
            // ---- fast reject (safe margin >= 1 pixel; NaN/inf fall through) ----
            float rcp = __frcp_rn(denom);
            float pxa = cx * rcp, pya = cy * rcp;
            if (pxa < -1.f || pxa > 160.f || pya < -1.f || pya > 88.f) continue;
            // ---- exact path (bit-identical to reference) ----
            float px = __fdiv_rn(cx, denom);
            float py = __fdiv_rn(cy, denom);
            float gx = (__fdiv_rn(px, 159.f) - 0.5f) * 2.f;
            float gy = (__fdiv_rn(py,  87.f) - 0.5f) * 2.f;
            if (gx > 1.f || gx < -1.f || gy > 1.f || gy < -1.f) continue;
            float xs = (gx + 1.f) * 0.5f * 159.f;
            float ys = (gy + 1.f) * 0.5f * 87.f;
            float xr = rintf(xs), yr = rintf(ys);
            if (!(xr >= 0.f && xr <= 159.f && yr >= 0.f && yr <= 87.f)) continue;
            float mv = __ldg(mask + cam * HWp + (int)yr * Ww + (int)xr);
            if (!(mv > 0.5f)) continue;
            if (count == 0)      { camA = cam; xsA = xs; ysA = ys; }
            else if (count == 1) { camB = cam; xsB = xs; ysB = ys; }
            count++;
            float dz = __fdiv_rn(vz, 100.f);
            if (cam == 0 || cam == 3 || cam == 4) z0 += dz; else z1 += dz;
        }
    }
    int lane = tid & 31;
    unsigned lt = (1u << lane) - 1u;
    unsigned m1 = __ballot_sync(0xFFFFFFFFu, count == 1);
    unsigned m2 = __ballot_sync(0xFFFFFFFFu, count == 2);
    int w1 = 0, w2o = 0;
    if (m1) {
        int ldr = __ffs(m1) - 1;
        if (lane == ldr) w1 = atomicAdd(&sh_cnt[0], __popc(m1));
        w1 = __shfl_sync(0xFFFFFFFFu, w1, ldr);
    }
    if (m2) {
        int ldr = __ffs(m2) - 1;
        if (lane == ldr) w2o = atomicAdd(&sh_cnt[1], __popc(m2));
        w2o = __shfl_sync(0xFFFFFFFFu, w2o, ldr);
    }
    __syncthreads();
    if (tid < 2) sh_base[tid] = atomicAdd(&g_cnt[tid], sh_cnt[tid]);
    __syncthreads();
    if (n < NVOX) {
        if (count == 1) {
            int idx = sh_base[0] + w1 + __popc(m1 & lt);
            g_q1[idx * 2]     = make_float4(__int_as_float(n), __int_as_float(camA), xsA, ysA);
            g_q1[idx * 2 + 1] = make_float4(z0 + z1, 0.f, 0.f, 0.f);
        } else if (count == 2) {
            int idx = sh_base[1] + w2o + __popc(m2 & lt);
            g_q2[idx * 2]     = make_float4(__int_as_float(n), __int_as_float(camA | (camB << 8)), xsA, ysA);
            g_q2[idx * 2 + 1] = make_float4(xsB, ysB, z0, z1);
        } else {
            // inactive voxel: zero-fill its output column (replaces global memset)
#pragma unroll
            for (int o = 0; o < 64; o++) out[(size_t)o * NVOX + n] = 0.f;
        }
    }
}

__device__ __forceinline__ float2 bilin(int cam, float xs, float ys, int lane) {
    float x0 = floorf(xs), y0 = floorf(ys);
    float wx1 = xs - x0, wx0 = 1.f - wx1;
    float wy1 = ys - y0, wy0 = 1.f - wy1;
    float ax = 0.f, ay = 0.f;
    const float2* base = (const float2*)(g_featT + (size_t)cam * HWp * CF);
#pragma unroll
    for (int corner = 0; corner < 4; corner++) {
        float xi = x0 + (float)(corner & 1);
        float yi = y0 + (float)(corner >> 1);
        if (xi >= 0.f && xi <= 159.f && yi >= 0.f && yi <= 87.f) {
            float w = ((corner & 1) ? wx1 : wx0) * ((corner >> 1) ? wy1 : wy0);
            int pixi = (int)yi * Ww + (int)xi;
            float2 v = __ldg(base + pixi * 32 + lane);
            ax += w * v.x;
            ay += w * v.y;
        }
    }
    return make_float2(ax, ay);
}

// Tiled GEMM over a queue: 64 outputs x 64 voxels per block tile, K = KR.
// Weights staged in smem from PRE-PACKED device-global arrays (coalesced copy,
// selected INSIDE the kernel via QIDX — device symbols never cross host boundary).
template<int KR, int QIDX>
__global__ __launch_bounds__(256) void gemm_kernel(
    const float* __restrict__ bias,   // [64]
    float* __restrict__ out)          // [64, NVOX]
{
    extern __shared__ float smem[];
    float2* w2  = (float2*)smem;                 // [KR][32] : {W[l][k], W[l+32][k]}
    float*  fsm = smem + KR * 64;                // [KR][68] feats (aliased as sout[64][65] later)
    float*  sb  = fsm + KR * 68;                 // [64]
    int*    s_n = (int*)(sb + 64);               // [64]

    int total = g_cnt[QIDX];
    if (blockIdx.x * 64 >= total) return;        // early exit BEFORE weight load

    int tid = threadIdx.x, lane = tid & 31, warp = tid >> 5;
    const float2* Wp = QIDX ? g_w2p : g_w1p;     // device-side symbol resolution
    // coalesced packed-weight copy: consecutive threads -> consecutive float2
    for (int i = tid; i < KR * 32; i += 256)
        w2[i] = __ldg(Wp + i);
    if (tid < 64) sb[tid] = bias[tid];

    const float4* q = QIDX ? g_q2 : g_q1;
    for (int tile = blockIdx.x; tile * 64 < total; tile += gridDim.x) {
        __syncthreads();   // weights ready / previous write-out done reading fsm alias
        // ---- gather: warp w fills columns [w*8, w*8+8) ----
#pragma unroll
        for (int j = 0; j < 8; j++) {
            int v = warp * 8 + j;
            int r = tile * 64 + v;
            if (r < total) {
                float4 ra = __ldg(q + r * 2);
                float4 rb = __ldg(q + r * 2 + 1);
                int n = __float_as_int(ra.x);
                if (QIDX == 0) {
                    int cam = __float_as_int(ra.y);
                    float2 a = bilin(cam, ra.z, ra.w, lane);
                    fsm[(2 * lane) * 68 + v]     = a.x;
                    fsm[(2 * lane + 1) * 68 + v] = a.y;
                    if (lane == 0) { fsm[64 * 68 + v] = rb.x; s_n[v] = n; }
                } else {
                    int cc = __float_as_int(ra.y);
                    int camA = cc & 255, camB = cc >> 8;
                    float2 a = bilin(camA, ra.z, ra.w, lane);
                    float2 b = bilin(camB, rb.x, rb.y, lane);
                    float2 h0 = make_float2(0.f, 0.f), h1 = make_float2(0.f, 0.f);
                    if (camA == 0 || camA == 3 || camA == 4) { h0.x += a.x; h0.y += a.y; }
                    else                                     { h1.x += a.x; h1.y += a.y; }
                    if (camB == 0 || camB == 3 || camB == 4) { h0.x += b.x; h0.y += b.y; }
                    else                                     { h1.x += b.x; h1.y += b.y; }
                    fsm[(2 * lane) * 68 + v]          = h0.x;
                    fsm[(2 * lane + 1) * 68 + v]      = h0.y;
                    fsm[(65 + 2 * lane) * 68 + v]     = h1.x;
                    fsm[(65 + 2 * lane + 1) * 68 + v] = h1.y;
                    if (lane == 0) { fsm[64 * 68 + v] = rb.z; fsm[129 * 68 + v] = rb.w; s_n[v] = n; }
                }
            } else if (lane == 0) s_n[v] = -1;
        }
        __syncthreads();
        // ---- GEMM: warp w -> voxels [w*8, w*8+8), thread -> outputs (lane, lane+32) ----
        float acc[16];
#pragma unroll
        for (int i = 0; i < 16; i++) acc[i] = 0.f;
        int vb = warp * 8;
#pragma unroll 5
        for (int k = 0; k < KR; k++) {
            float2 wv = w2[k * 32 + lane];
            float4 f0 = *(const float4*)(fsm + k * 68 + vb);
            float4 f1 = *(const float4*)(fsm + k * 68 + vb + 4);
            acc[0]  = fmaf(wv.x, f0.x, acc[0]);  acc[1]  = fmaf(wv.y, f0.x, acc[1]);
            acc[2]  = fmaf(wv.x, f0.y, acc[2]);  acc[3]  = fmaf(wv.y, f0.y, acc[3]);
            acc[4]  = fmaf(wv.x, f0.z, acc[4]);  acc[5]  = fmaf(wv.y, f0.z, acc[5]);
            acc[6]  = fmaf(wv.x, f0.w, acc[6]);  acc[7]  = fmaf(wv.y, f0.w, acc[7]);
            acc[8]  = fmaf(wv.x, f1.x, acc[8]);  acc[9]  = fmaf(wv.y, f1.x, acc[9]);
            acc[10] = fmaf(wv.x, f1.y, acc[10]); acc[11] = fmaf(wv.y, f1.y, acc[11]);
            acc[12] = fmaf(wv.x, f1.z, acc[12]); acc[13] = fmaf(wv.y, f1.z, acc[13]);
            acc[14] = fmaf(wv.x, f1.w, acc[14]); acc[15] = fmaf(wv.y, f1.w, acc[15]);
        }
        __syncthreads();   // everyone done reading fsm; reuse as sout[64][65]
        float* som = fsm;
        float b0 = sb[lane], b1 = sb[lane + 32];
#pragma unroll
        for (int j = 0; j < 8; j++) {
            som[lane * 65 + vb + j]        = elu1(acc[2 * j]     + b0);
            som[(lane + 32) * 65 + vb + j] = elu1(acc[2 * j + 1] + b1);
        }
        __syncthreads();
        // ---- write-out: row-major, near-coalesced over clustered queue columns ----
#pragma unroll
        for (int i = tid; i < 64 * 64; i += 256) {
            int o = i >> 6, v = i & 63;
            int nn = s_n[v];
            if (nn >= 0) out[(size_t)o * NVOX + nn] = som[o * 65 + v];
        }
    }
}

extern "C" void kernel_launch(void* const* d_in, const int* in_sizes, int n_in,
                              void* d_out, int out_size) {
    const float* feat = (const float*)d_in[0];
    const float* mask = (const float*)d_in[1];
    const float* K    = (const float*)d_in[2];
    const float* ext  = (const float*)d_in[3];
    const float* w_no = (const float*)d_in[4];
    const float* b_no = (const float*)d_in[5];
    const float* w_o  = (const float*)d_in[6];
    const float* b_o  = (const float*)d_in[7];
    float* out = (float*)d_out;

    static cudaStream_t s1 = nullptr, s2 = nullptr;
    static cudaEvent_t e0 = nullptr, e_t = nullptr, e_p = nullptr, e_c = nullptr, e_g1 = nullptr;
    if (!s1) {
        cudaStreamCreateWithFlags(&s1, cudaStreamNonBlocking);
        cudaStreamCreateWithFlags(&s2, cudaStreamNonBlocking);
        cudaEventCreateWithFlags(&e0,  cudaEventDisableTiming);
        cudaEventCreateWithFlags(&e_t, cudaEventDisableTiming);
        cudaEventCreateWithFlags(&e_p, cudaEventDisableTiming);
        cudaEventCreateWithFlags(&e_c, cudaEventDisableTiming);
        cudaEventCreateWithFlags(&e_g1, cudaEventDisableTiming);
    }

    const int smem1 = (65 * 64  + 65 * 68  + 64 + 64) * 4;   // 34832
    const int smem2 = (130 * 64 + 130 * 68 + 64 + 64) * 4;   // 69152
    cudaFuncSetAttribute(gemm_kernel<65, 0>,  cudaFuncAttributeMaxDynamicSharedMemorySize, smem1);
    cudaFuncSetAttribute(gemm_kernel<130, 1>, cudaFuncAttributeMaxDynamicSharedMemorySize, smem2);

    // fork: transpose on s1, pack on s2, init+classify (+zero-fill) on capture stream
    cudaEventRecord(e0, 0);
    cudaStreamWaitEvent(s1, e0, 0);
    cudaStreamWaitEvent(s2, e0, 0);

    dim3 tg(HWp / 32, CF / 32, NC);   // 440 x 2 x 6
    transpose_kernel<<<tg, dim3(32, 8), 0, s1>>>(feat);
    cudaEventRecord(e_t, s1);

    pack_kernel<<<17, 256, 0, s2>>>(w_no, w_o);
    cudaEventRecord(e_p, s2);

    init_kernel<<<1, 32>>>();
    classify_kernel<<<(NVOX + 255) / 256, 256>>>(mask, K, ext, out);
    cudaEventRecord(e_c, 0);

    // join: gemms need classify + transpose + pack
    cudaStreamWaitEvent(0, e_t, 0);
    cudaStreamWaitEvent(0, e_p, 0);
    cudaStreamWaitEvent(s1, e_c, 0);
    cudaStreamWaitEvent(s1, e_p, 0);

    gemm_kernel<130, 1><<<304, 256, smem2, 0>>>(b_o, out);
    gemm_kernel<65, 0><<<304, 256, smem1, s1>>>(b_no, out);
    cudaEventRecord(e_g1, s1);
    cudaStreamWaitEvent(0, e_g1, 0);
}

// round 11
// speedup vs baseline: 1.8142x; 1.2348x over previous
#include <cuda_runtime.h>

#define NC    6
#define CF    64
#define Hh    88
#define Ww    160
#define HWp   (Hh*Ww)          // 14080
#define XD    100
#define YD    100
#define ZD    20
#define NVOX  (XD*YD*ZD)       // 200000

// scratch
__device__ float  g_featT[NC * HWp * CF];   // channel-last features [cam][H][W][C]
__device__ float4 g_q1[NVOX * 2];           // count==1 records
__device__ float4 g_q2[NVOX * 2];           // count==2 records
__device__ int    g_cnt[2];
__device__ float2 g_w1p[65 * 32];           // packed w_no: [k][lane]={W[l][k],W[l+32][k]}
__device__ float2 g_w2p[130 * 32];          // packed w_o
__device__ unsigned char g_flag[NVOX];      // 1 = active (count 1 or 2)

__device__ __forceinline__ float elu1(float x) { return x > 0.f ? x : expm1f(x); }

__global__ void init_kernel() {
    if (threadIdx.x < 2) g_cnt[threadIdx.x] = 0;
}

__global__ void pack_kernel(const float* __restrict__ w_no, const float* __restrict__ w_o) {
    int i = blockIdx.x * 256 + threadIdx.x;
    if (i < 65 * 32) {
        int k = i >> 5, l = i & 31;
        g_w1p[i] = make_float2(w_no[l * 65 + k], w_no[(l + 32) * 65 + k]);
    }
    if (i < 130 * 32) {
        int k = i >> 5, l = i & 31;
        g_w2p[i] = make_float2(w_o[l * 130 + k], w_o[(l + 32) * 130 + k]);
    }
}

__global__ void transpose_kernel(const float* __restrict__ feat) {
    __shared__ float tile[32][33];
    int cam = blockIdx.z;
    int c0  = blockIdx.y * 32;
    int p0  = blockIdx.x * 32;
    int tx = threadIdx.x, ty = threadIdx.y;
    const float* src = feat + (size_t)cam * CF * HWp;
#pragma unroll
    for (int i = ty; i < 32; i += 8)
        tile[i][tx] = src[(c0 + i) * HWp + p0 + tx];
    __syncthreads();
    float* dst = g_featT + (size_t)cam * HWp * CF;
#pragma unroll
    for (int i = ty; i < 32; i += 8)
        dst[(p0 + i) * CF + c0 + tx] = tile[tx][i];
}

__global__ __launch_bounds__(256) void classify_kernel(
    const float* __restrict__ mask,
    const float* __restrict__ Kin,
    const float* __restrict__ Ein)
{
    __shared__ float sE[96], sK[96];
    __shared__ int sh_cnt[2], sh_base[2];
    int tid = threadIdx.x;
    if (tid < 96) { sE[tid] = Ein[tid]; sK[tid] = Kin[tid]; }
    if (tid < 2) sh_cnt[tid] = 0;
    __syncthreads();

    int n = blockIdx.x * 256 + tid;
    int count = 0, camA = 0, camB = 0;
    float xsA = 0.f, ysA = 0.f, xsB = 0.f, ysB = 0.f, z0 = 0.f, z1 = 0.f;
    if (n < NVOX) {
        int x = n % XD, y = (n / XD) % YD, z = n / (XD * YD);
        float X = -50.f + (float)x;
        float Y = -50.f + (float)y;
        float Z = -15.f + 1.5f * (float)z;
#pragma unroll
        for (int cam = 0; cam < NC; cam++) {
            const float* E  = sE + cam * 16;
            const float* Km = sK + cam * 16;
            float vx = E[0] * X + E[1] * Y + E[2]  * Z + E[3];
            float vy = E[4] * X + E[5] * Y + E[6]  * Z + E[7];
            float vz = E[8] * X + E[9] * Y + E[10] * Z + E[11];
            if (!(vz > 0.f)) continue;
            float cx = Km[0] * vx + Km[1] * vy + Km[2]  * vz;
            float cy = Km[4] * vx + Km[5] * vy + Km[6]  * vz;
            float cz = Km[8] * vx + Km[9] * vy + Km[10] * vz;
            float denom = cz + 1e-8f;
            // ---- fast reject (safe margin >= 1 pixel; NaN/inf fall through) ----
            float rcp = __frcp_rn(denom);
            float pxa = cx * rcp, pya = cy * rcp;
            if (pxa < -1.f || pxa > 160.f || pya < -1.f || pya > 88.f) continue;
            // ---- exact path (bit-identical to reference) ----
            float px = __fdiv_rn(cx, denom);
            float py = __fdiv_rn(cy, denom);
            float gx = (__fdiv_rn(px, 159.f) - 0.5f) * 2.f;
            float gy = (__fdiv_rn(py,  87.f) - 0.5f) * 2.f;
            if (gx > 1.f || gx < -1.f || gy > 1.f || gy < -1.f) continue;
            float xs = (gx + 1.f) * 0.5f * 159.f;
            float ys = (gy + 1.f) * 0.5f * 87.f;
            float xr = rintf(xs), yr = rintf(ys);
            if (!(xr >= 0.f && xr <= 159.f && yr >= 0.f && yr <= 87.f)) continue;
            float mv = __ldg(mask + cam * HWp + (int)yr * Ww + (int)xr);
            if (!(mv > 0.5f)) continue;
            if (count == 0)      { camA = cam; xsA = xs; ysA = ys; }
            else if (count == 1) { camB = cam; xsB = xs; ysB = ys; }
            count++;
            float dz = __fdiv_rn(vz, 100.f);
            if (cam == 0 || cam == 3 || cam == 4) z0 += dz; else z1 += dz;
        }
    }
    int lane = tid & 31;
    unsigned lt = (1u << lane) - 1u;
    unsigned m1 = __ballot_sync(0xFFFFFFFFu, count == 1);
    unsigned m2 = __ballot_sync(0xFFFFFFFFu, count == 2);
    int w1 = 0, w2o = 0;
    if (m1) {
        int ldr = __ffs(m1) - 1;
        if (lane == ldr) w1 = atomicAdd(&sh_cnt[0], __popc(m1));
        w1 = __shfl_sync(0xFFFFFFFFu, w1, ldr);
    }
    if (m2) {
        int ldr = __ffs(m2) - 1;
        if (lane == ldr) w2o = atomicAdd(&sh_cnt[1], __popc(m2));
        w2o = __shfl_sync(0xFFFFFFFFu, w2o, ldr);
    }
    __syncthreads();
    if (tid < 2) sh_base[tid] = atomicAdd(&g_cnt[tid], sh_cnt[tid]);
    __syncthreads();
    if (n < NVOX) {
        g_flag[n] = (count == 1 || count == 2) ? 1 : 0;
        if (count == 1) {
            int idx = sh_base[0] + w1 + __popc(m1 & lt);
            g_q1[idx * 2]     = make_float4(__int_as_float(n), __int_as_float(camA), xsA, ysA);
            g_q1[idx * 2 + 1] = make_float4(z0 + z1, 0.f, 0.f, 0.f);
        } else if (count == 2) {
            int idx = sh_base[1] + w2o + __popc(m2 & lt);
            g_q2[idx * 2]     = make_float4(__int_as_float(n), __int_as_float(camA | (camB << 8)), xsA, ysA);
            g_q2[idx * 2 + 1] = make_float4(xsB, ysB, z0, z1);
        }
    }
}

// zero-fill inactive voxel columns; runs concurrent with the GEMMs
__global__ __launch_bounds__(256) void fill_kernel(float* __restrict__ out) {
    int n = blockIdx.x * 256 + threadIdx.x;
    if (n < NVOX && !g_flag[n]) {
#pragma unroll
        for (int o = 0; o < 64; o++) out[(size_t)o * NVOX + n] = 0.f;
    }
}

__device__ __forceinline__ float2 bilin(int cam, float xs, float ys, int lane) {
    float x0 = floorf(xs), y0 = floorf(ys);
    float wx1 = xs - x0, wx0 = 1.f - wx1;
    float wy1 = ys - y0, wy0 = 1.f - wy1;
    float ax = 0.f, ay = 0.f;
    const float2* base = (const float2*)(g_featT + (size_t)cam * HWp * CF);
#pragma unroll
    for (int corner = 0; corner < 4; corner++) {
        float xi = x0 + (float)(corner & 1);
        float yi = y0 + (float)(corner >> 1);
        if (xi >= 0.f && xi <= 159.f && yi >= 0.f && yi <= 87.f) {
            float w = ((corner & 1) ? wx1 : wx0) * ((corner >> 1) ? wy1 : wy0);
            int pixi = (int)yi * Ww + (int)xi;
            float2 v = __ldg(base + pixi * 32 + lane);
            ax += w * v.x;
            ay += w * v.y;
        }
    }
    return make_float2(ax, ay);
}

// Tiled GEMM over a queue: 64 outputs x 64 voxels per block tile, K = KR.
// Weights from pre-packed device globals (coalesced smem fill);
// gather prefetches all 8 records per warp before bilinears (one MLP batch).
template<int KR, int QIDX>
__global__ __launch_bounds__(256) void gemm_kernel(
    const float* __restrict__ bias,   // [64]
    float* __restrict__ out)          // [64, NVOX]
{
    extern __shared__ float smem[];
    float2* w2  = (float2*)smem;                 // [KR][32] : {W[l][k], W[l+32][k]}
    float*  fsm = smem + KR * 64;                // [KR][68] feats (aliased as sout[64][65] later)
    float*  sb  = fsm + KR * 68;                 // [64]
    int*    s_n = (int*)(sb + 64);               // [64]

    int total = g_cnt[QIDX];
    if (blockIdx.x * 64 >= total) return;        // early exit BEFORE weight load

    int tid = threadIdx.x, lane = tid & 31, warp = tid >> 5;
    const float2* Wp = QIDX ? g_w2p : g_w1p;
    for (int i = tid; i < KR * 32; i += 256)     // coalesced packed copy
        w2[i] = __ldg(Wp + i);
    if (tid < 64) sb[tid] = bias[tid];

    const float4* q = QIDX ? g_q2 : g_q1;
    for (int tile = blockIdx.x; tile * 64 < total; tile += gridDim.x) {
        __syncthreads();   // weights ready / previous write-out done reading fsm alias
        // ---- gather: prefetch all 8 records, then independent bilinears ----
        float4 ra[8], rb[8];
#pragma unroll
        for (int j = 0; j < 8; j++) {
            int r = tile * 64 + warp * 8 + j;
            if (r < total) {
                ra[j] = __ldg(q + r * 2);
                rb[j] = __ldg(q + r * 2 + 1);
            } else {
                ra[j] = make_float4(__int_as_float(-1), 0.f, 0.f, 0.f);
                rb[j] = make_float4(0.f, 0.f, 0.f, 0.f);
            }
        }
#pragma unroll
        for (int j = 0; j < 8; j++) {
            int v = warp * 8 + j;
            int n = __float_as_int(ra[j].x);
            if (n >= 0) {
                if (QIDX == 0) {
                    int cam = __float_as_int(ra[j].y);
                    float2 a = bilin(cam, ra[j].z, ra[j].w, lane);
                    fsm[(2 * lane) * 68 + v]     = a.x;
                    fsm[(2 * lane + 1) * 68 + v] = a.y;
                    if (lane == 0) { fsm[64 * 68 + v] = rb[j].x; s_n[v] = n; }
                } else {
                    int cc = __float_as_int(ra[j].y);
                    int camA = cc & 255, camB = cc >> 8;
                    float2 a = bilin(camA, ra[j].z, ra[j].w, lane);
                    float2 b = bilin(camB, rb[j].x, rb[j].y, lane);
                    float2 h0 = make_float2(0.f, 0.f), h1 = make_float2(0.f, 0.f);
                    if (camA == 0 || camA == 3 || camA == 4) { h0.x += a.x; h0.y += a.y; }
                    else                                     { h1.x += a.x; h1.y += a.y; }
                    if (camB == 0 || camB == 3 || camB == 4) { h0.x += b.x; h0.y += b.y; }
                    else                                     { h1.x += b.x; h1.y += b.y; }
                    fsm[(2 * lane) * 68 + v]          = h0.x;
                    fsm[(2 * lane + 1) * 68 + v]      = h0.y;
                    fsm[(65 + 2 * lane) * 68 + v]     = h1.x;
                    fsm[(65 + 2 * lane + 1) * 68 + v] = h1.y;
                    if (lane == 0) { fsm[64 * 68 + v] = rb[j].z; fsm[129 * 68 + v] = rb[j].w; s_n[v] = n; }
                }
            } else if (lane == 0) s_n[v] = -1;
        }
        __syncthreads();
        // ---- GEMM: warp w -> voxels [w*8, w*8+8), thread -> outputs (lane, lane+32) ----
        float acc[16];
#pragma unroll
        for (int i = 0; i < 16; i++) acc[i] = 0.f;
        int vb = warp * 8;
#pragma unroll 5
        for (int k = 0; k < KR; k++) {
            float2 wv = w2[k * 32 + lane];
            float4 f0 = *(const float4*)(fsm + k * 68 + vb);
            float4 f1 = *(const float4*)(fsm + k * 68 + vb + 4);
            acc[0]  = fmaf(wv.x, f0.x, acc[0]);  acc[1]  = fmaf(wv.y, f0.x, acc[1]);
            acc[2]  = fmaf(wv.x, f0.y, acc[2]);  acc[3]  = fmaf(wv.y, f0.y, acc[3]);
            acc[4]  = fmaf(wv.x, f0.z, acc[4]);  acc[5]  = fmaf(wv.y, f0.z, acc[5]);
            acc[6]  = fmaf(wv.x, f0.w, acc[6]);  acc[7]  = fmaf(wv.y, f0.w, acc[7]);
            acc[8]  = fmaf(wv.x, f1.x, acc[8]);  acc[9]  = fmaf(wv.y, f1.x, acc[9]);
            acc[10] = fmaf(wv.x, f1.y, acc[10]); acc[11] = fmaf(wv.y, f1.y, acc[11]);
            acc[12] = fmaf(wv.x, f1.z, acc[12]); acc[13] = fmaf(wv.y, f1.z, acc[13]);
            acc[14] = fmaf(wv.x, f1.w, acc[14]); acc[15] = fmaf(wv.y, f1.w, acc[15]);
        }
        __syncthreads();   // everyone done reading fsm; reuse as sout[64][65]
        float* som = fsm;
        float b0 = sb[lane], b1 = sb[lane + 32];
#pragma unroll
        for (int j = 0; j < 8; j++) {
            som[lane * 65 + vb + j]        = elu1(acc[2 * j]     + b0);
            som[(lane + 32) * 65 + vb + j] = elu1(acc[2 * j + 1] + b1);
        }
        __syncthreads();
        // ---- write-out: row-major, near-coalesced over clustered queue columns ----
#pragma unroll
        for (int i = tid; i < 64 * 64; i += 256) {
            int o = i >> 6, v = i & 63;
            int nn = s_n[v];
            if (nn >= 0) out[(size_t)o * NVOX + nn] = som[o * 65 + v];
        }
    }
}

extern "C" void kernel_launch(void* const* d_in, const int* in_sizes, int n_in,
                              void* d_out, int out_size) {
    const float* feat = (const float*)d_in[0];
    const float* mask = (const float*)d_in[1];
    const float* K    = (const float*)d_in[2];
    const float* ext  = (const float*)d_in[3];
    const float* w_no = (const float*)d_in[4];
    const float* b_no = (const float*)d_in[5];
    const float* w_o  = (const float*)d_in[6];
    const float* b_o  = (const float*)d_in[7];
    float* out = (float*)d_out;

    static cudaStream_t s1 = nullptr, s2 = nullptr;
    static cudaEvent_t e0 = nullptr, e_t = nullptr, e_p = nullptr, e_c = nullptr,
                       e_g1 = nullptr, e_f = nullptr;
    if (!s1) {
        cudaStreamCreateWithFlags(&s1, cudaStreamNonBlocking);
        cudaStreamCreateWithFlags(&s2, cudaStreamNonBlocking);
        cudaEventCreateWithFlags(&e0,  cudaEventDisableTiming);
        cudaEventCreateWithFlags(&e_t, cudaEventDisableTiming);
        cudaEventCreateWithFlags(&e_p, cudaEventDisableTiming);
        cudaEventCreateWithFlags(&e_c, cudaEventDisableTiming);
        cudaEventCreateWithFlags(&e_g1, cudaEventDisableTiming);
        cudaEventCreateWithFlags(&e_f, cudaEventDisableTiming);
    }

    const int smem1 = (65 * 64  + 65 * 68  + 64 + 64) * 4;   // 34832
    const int smem2 = (130 * 64 + 130 * 68 + 64 + 64) * 4;   // 69152
    cudaFuncSetAttribute(gemm_kernel<65, 0>,  cudaFuncAttributeMaxDynamicSharedMemorySize, smem1);
    cudaFuncSetAttribute(gemm_kernel<130, 1>, cudaFuncAttributeMaxDynamicSharedMemorySize, smem2);

    // fork: transpose on s1, pack on s2, init+classify on capture stream
    cudaEventRecord(e0, 0);
    cudaStreamWaitEvent(s1, e0, 0);
    cudaStreamWaitEvent(s2, e0, 0);

    dim3 tg(HWp / 32, CF / 32, NC);   // 440 x 2 x 6
    transpose_kernel<<<tg, dim3(32, 8), 0, s1>>>(feat);
    cudaEventRecord(e_t, s1);

    pack_kernel<<<17, 256, 0, s2>>>(w_no, w_o);
    cudaEventRecord(e_p, s2);

    init_kernel<<<1, 32>>>();
    classify_kernel<<<(NVOX + 255) / 256, 256>>>(mask, K, ext);
    cudaEventRecord(e_c, 0);

    // gemm<130> on stream 0: needs transpose + pack (classify in order)
    cudaStreamWaitEvent(0, e_t, 0);
    cudaStreamWaitEvent(0, e_p, 0);
    gemm_kernel<130, 1><<<304, 256, smem2, 0>>>(b_o, out);

    // gemm<65> on s1: needs classify + pack (transpose in order)
    cudaStreamWaitEvent(s1, e_c, 0);
    cudaStreamWaitEvent(s1, e_p, 0);
    gemm_kernel<65, 0><<<304, 256, smem1, s1>>>(b_no, out);
    cudaEventRecord(e_g1, s1);

    // fill on s2: needs classify only; runs concurrent with gemms
    cudaStreamWaitEvent(s2, e_c, 0);
    fill_kernel<<<(NVOX + 255) / 256, 256, 0, s2>>>(out);
    cudaEventRecord(e_f, s2);

    cudaStreamWaitEvent(0, e_g1, 0);
    cudaStreamWaitEvent(0, e_f, 0);
}

// round 12
// speedup vs baseline: 2.0133x; 1.1097x over previous
#include <cuda_runtime.h>

#define NC    6
#define CF    64
#define Hh    88
#define Ww    160
#define HWp   (Hh*Ww)          // 14080
#define XD    100
#define YD    100
#define ZD    20
#define NVOX  (XD*YD*ZD)       // 200000

// scratch
__device__ float  g_featT[NC * HWp * CF];   // channel-last features [cam][H][W][C]
__device__ float4 g_q1[NVOX * 2];           // count==1 records
__device__ float4 g_q2[NVOX * 2];           // count==2 records
__device__ int    g_cnt[2];
__device__ float2 g_w1p[65 * 32];           // packed w_no: [k][lane]={W[l][k],W[l+32][k]}
__device__ float2 g_w2p[130 * 32];          // packed w_o
__device__ unsigned char g_flag[NVOX];      // 1 = active (count 1 or 2)

__device__ __forceinline__ float elu1(float x) { return x > 0.f ? x : expm1f(x); }

__global__ void init_kernel() {
    if (threadIdx.x < 2) g_cnt[threadIdx.x] = 0;
}

__global__ void pack_kernel(const float* __restrict__ w_no, const float* __restrict__ w_o) {
    int i = blockIdx.x * 256 + threadIdx.x;
    if (i < 65 * 32) {
        int k = i >> 5, l = i & 31;
        g_w1p[i] = make_float2(w_no[l * 65 + k], w_no[(l + 32) * 65 + k]);
    }
    if (i < 130 * 32) {
        int k = i >> 5, l = i & 31;
        g_w2p[i] = make_float2(w_o[l * 130 + k], w_o[(l + 32) * 130 + k]);
    }
}

__global__ void transpose_kernel(const float* __restrict__ feat) {
    __shared__ float tile[32][33];
    int cam = blockIdx.z;
    int c0  = blockIdx.y * 32;
    int p0  = blockIdx.x * 32;
    int tx = threadIdx.x, ty = threadIdx.y;
    const float* src = feat + (size_t)cam * CF * HWp;
#pragma unroll
    for (int i = ty; i < 32; i += 8)
        tile[i][tx] = src[(c0 + i) * HWp + p0 + tx];
    __syncthreads();
    float* dst = g_featT + (size_t)cam * HWp * CF;
#pragma unroll
    for (int i = ty; i < 32; i += 8)
        dst[(p0 + i) * CF + c0 + tx] = tile[tx][i];
}

__global__ __launch_bounds__(256) void classify_kernel(
    const float* __restrict__ mask,
    const float* __restrict__ Kin,
    const float* __restrict__ Ein)
{
    __shared__ float sE[96], sK[96];
    __shared__ int sh_cnt[2], sh_base[2];
    int tid = threadIdx.x;
    if (tid < 96) { sE[tid] = Ein[tid]; sK[tid] = Kin[tid]; }
    if (tid < 2) sh_cnt[tid] = 0;
    __syncthreads();

    int n = blockIdx.x * 256 + tid;
    int count = 0, camA = 0, camB = 0;
    float xsA = 0.f, ysA = 0.f, xsB = 0.f, ysB = 0.f, z0 = 0.f, z1 = 0.f;
    if (n < NVOX) {
        int x = n % XD, y = (n / XD) % YD, z = n / (XD * YD);
        float X = -50.f + (float)x;
        float Y = -50.f + (float)y;
        float Z = -15.f + 1.5f * (float)z;
#pragma unroll
        for (int cam = 0; cam < NC; cam++) {
            const float* E  = sE + cam * 16;
            const float* Km = sK + cam * 16;
            float vx = E[0] * X + E[1] * Y + E[2]  * Z + E[3];
            float vy = E[4] * X + E[5] * Y + E[6]  * Z + E[7];
            float vz = E[8] * X + E[9] * Y + E[10] * Z + E[11];
            if (!(vz > 0.f)) continue;
            float cx = Km[0] * vx + Km[1] * vy + Km[2]  * vz;
            float cy = Km[4] * vx + Km[5] * vy + Km[6]  * vz;
            float cz = Km[8] * vx + Km[9] * vy + Km[10] * vz;
            float denom = cz + 1e-8f;
            // ---- fast reject (safe margin >= 1 pixel; NaN/inf fall through) ----
            float rcp = __frcp_rn(denom);
            float pxa = cx * rcp, pya = cy * rcp;
            if (pxa < -1.f || pxa > 160.f || pya < -1.f || pya > 88.f) continue;
            // ---- exact path (bit-identical to reference) ----
            float px = __fdiv_rn(cx, denom);
            float py = __fdiv_rn(cy, denom);
            float gx = (__fdiv_rn(px, 159.f) - 0.5f) * 2.f;
            float gy = (__fdiv_rn(py,  87.f) - 0.5f) * 2.f;
            if (gx > 1.f || gx < -1.f || gy > 1.f || gy < -1.f) continue;
            float xs = (gx + 1.f) * 0.5f * 159.f;
            float ys = (gy + 1.f) * 0.5f * 87.f;
            float xr = rintf(xs), yr = rintf(ys);
            if (!(xr >= 0.f && xr <= 159.f && yr >= 0.f && yr <= 87.f)) continue;
            float mv = __ldg(mask + cam * HWp + (int)yr * Ww + (int)xr);
            if (!(mv > 0.5f)) continue;
            if (count == 0)      { camA = cam; xsA = xs; ysA = ys; }
            else if (count == 1) { camB = cam; xsB = xs; ysB = ys; }
            count++;
            float dz = __fdiv_rn(vz, 100.f);
            if (cam == 0 || cam == 3 || cam == 4) z0 += dz; else z1 += dz;
        }
    }
    int lane = tid & 31;
    unsigned lt = (1u << lane) - 1u;
    unsigned m1 = __ballot_sync(0xFFFFFFFFu, count == 1);
    unsigned m2 = __ballot_sync(0xFFFFFFFFu, count == 2);
    int w1 = 0, w2o = 0;
    if (m1) {
        int ldr = __ffs(m1) - 1;
        if (lane == ldr) w1 = atomicAdd(&sh_cnt[0], __popc(m1));
        w1 = __shfl_sync(0xFFFFFFFFu, w1, ldr);
    }
    if (m2) {
        int ldr = __ffs(m2) - 1;
        if (lane == ldr) w2o = atomicAdd(&sh_cnt[1], __popc(m2));
        w2o = __shfl_sync(0xFFFFFFFFu, w2o, ldr);
    }
    __syncthreads();
    if (tid < 2) sh_base[tid] = atomicAdd(&g_cnt[tid], sh_cnt[tid]);
    __syncthreads();
    if (n < NVOX) {
        g_flag[n] = (count == 1 || count == 2) ? 1 : 0;
        if (count == 1) {
            int idx = sh_base[0] + w1 + __popc(m1 & lt);
            g_q1[idx * 2]     = make_float4(__int_as_float(n), __int_as_float(camA), xsA, ysA);
            g_q1[idx * 2 + 1] = make_float4(z0 + z1, 0.f, 0.f, 0.f);
        } else if (count == 2) {
            int idx = sh_base[1] + w2o + __popc(m2 & lt);
            g_q2[idx * 2]     = make_float4(__int_as_float(n), __int_as_float(camA | (camB << 8)), xsA, ysA);
            g_q2[idx * 2 + 1] = make_float4(xsB, ysB, z0, z1);
        }
    }
}

// zero-fill inactive voxel columns; runs concurrent with the GEMMs
__global__ __launch_bounds__(256) void fill_kernel(float* __restrict__ out) {
    int n = blockIdx.x * 256 + threadIdx.x;
    if (n < NVOX && !g_flag[n]) {
#pragma unroll
        for (int o = 0; o < 64; o++) out[(size_t)o * NVOX + n] = 0.f;
    }
}

__device__ __forceinline__ float2 bilin(int cam, float xs, float ys, int lane) {
    float x0 = floorf(xs), y0 = floorf(ys);
    float wx1 = xs - x0, wx0 = 1.f - wx1;
    float wy1 = ys - y0, wy0 = 1.f - wy1;
    float ax = 0.f, ay = 0.f;
    const float2* base = (const float2*)(g_featT + (size_t)cam * HWp * CF);
#pragma unroll
    for (int corner = 0; corner < 4; corner++) {
        float xi = x0 + (float)(corner & 1);
        float yi = y0 + (float)(corner >> 1);
        if (xi >= 0.f && xi <= 159.f && yi >= 0.f && yi <= 87.f) {
            float w = ((corner & 1) ? wx1 : wx0) * ((corner >> 1) ? wy1 : wy0);
            int pixi = (int)yi * Ww + (int)xi;
            float2 v = __ldg(base + pixi * 32 + lane);
            ax += w * v.x;
            ay += w * v.y;
        }
    }
    return make_float2(ax, ay);
}

// Tiled GEMM over a queue: 64 outputs x 64 voxels per block tile, K = KR.
// Weights from pre-packed device globals (coalesced smem fill);
// gather prefetches all 8 records per warp before bilinears (one MLP batch).
template<int KR, int QIDX>
__global__ __launch_bounds__(256) void gemm_kernel(
    const float* __restrict__ bias,   // [64]
    float* __restrict__ out)          // [64, NVOX]
{
    extern __shared__ float smem[];
    float2* w2  = (float2*)smem;                 // [KR][32] : {W[l][k], W[l+32][k]}
    float*  fsm = smem + KR * 64;                // [KR][68] feats (aliased as sout[64][65] later)
    float*  sb  = fsm + KR * 68;                 // [64]
    int*    s_n = (int*)(sb + 64);               // [64]

    int total = g_cnt[QIDX];
    if (blockIdx.x * 64 >= total) return;        // early exit BEFORE weight load

    int tid = threadIdx.x, lane = tid & 31, warp = tid >> 5;
    const float2* Wp = QIDX ? g_w2p : g_w1p;
    for (int i = tid; i < KR * 32; i += 256)     // coalesced packed copy
        w2[i] = __ldg(Wp + i);
    if (tid < 64) sb[tid] = bias[tid];

    const float4* q = QIDX ? g_q2 : g_q1;
    for (int tile = blockIdx.x; tile * 64 < total; tile += gridDim.x) {
        __syncthreads();   // weights ready / previous write-out done reading fsm alias
        // ---- gather: prefetch all 8 records, then independent bilinears ----
        float4 ra[8], rb[8];
#pragma unroll
        for (int j = 0; j < 8; j++) {
            int r = tile * 64 + warp * 8 + j;
            if (r < total) {
                ra[j] = __ldg(q + r * 2);
                rb[j] = __ldg(q + r * 2 + 1);
            } else {
                ra[j] = make_float4(__int_as_float(-1), 0.f, 0.f, 0.f);
                rb[j] = make_float4(0.f, 0.f, 0.f, 0.f);
            }
        }
#pragma unroll
        for (int j = 0; j < 8; j++) {
            int v = warp * 8 + j;
            int n = __float_as_int(ra[j].x);
            if (n >= 0) {
                if (QIDX == 0) {
                    int cam = __float_as_int(ra[j].y);
                    float2 a = bilin(cam, ra[j].z, ra[j].w, lane);
                    fsm[(2 * lane) * 68 + v]     = a.x;
                    fsm[(2 * lane + 1) * 68 + v] = a.y;
                    if (lane == 0) { fsm[64 * 68 + v] = rb[j].x; s_n[v] = n; }
                } else {
                    int cc = __float_as_int(ra[j].y);
                    int camA = cc & 255, camB = cc >> 8;
                    float2 a = bilin(camA, ra[j].z, ra[j].w, lane);
                    float2 b = bilin(camB, rb[j].x, rb[j].y, lane);
                    float2 h0 = make_float2(0.f, 0.f), h1 = make_float2(0.f, 0.f);
                    if (camA == 0 || camA == 3 || camA == 4) { h0.x += a.x; h0.y += a.y; }
                    else                                     { h1.x += a.x; h1.y += a.y; }
                    if (camB == 0 || camB == 3 || camB == 4) { h0.x += b.x; h0.y += b.y; }
                    else                                     { h1.x += b.x; h1.y += b.y; }
                    fsm[(2 * lane) * 68 + v]          = h0.x;
                    fsm[(2 * lane + 1) * 68 + v]      = h0.y;
                    fsm[(65 + 2 * lane) * 68 + v]     = h1.x;
                    fsm[(65 + 2 * lane + 1) * 68 + v] = h1.y;
                    if (lane == 0) { fsm[64 * 68 + v] = rb[j].z; fsm[129 * 68 + v] = rb[j].w; s_n[v] = n; }
                }
            } else if (lane == 0) s_n[v] = -1;
        }
        __syncthreads();
        // ---- GEMM: warp w -> voxels [w*8, w*8+8), thread -> outputs (lane, lane+32) ----
        float acc[16];
#pragma unroll
        for (int i = 0; i < 16; i++) acc[i] = 0.f;
        int vb = warp * 8;
#pragma unroll 5
        for (int k = 0; k < KR; k++) {
            float2 wv = w2[k * 32 + lane];
            float4 f0 = *(const float4*)(fsm + k * 68 + vb);
            float4 f1 = *(const float4*)(fsm + k * 68 + vb + 4);
            acc[0]  = fmaf(wv.x, f0.x, acc[0]);  acc[1]  = fmaf(wv.y, f0.x, acc[1]);
            acc[2]  = fmaf(wv.x, f0.y, acc[2]);  acc[3]  = fmaf(wv.y, f0.y, acc[3]);
            acc[4]  = fmaf(wv.x, f0.z, acc[4]);  acc[5]  = fmaf(wv.y, f0.z, acc[5]);
            acc[6]  = fmaf(wv.x, f0.w, acc[6]);  acc[7]  = fmaf(wv.y, f0.w, acc[7]);
            acc[8]  = fmaf(wv.x, f1.x, acc[8]);  acc[9]  = fmaf(wv.y, f1.x, acc[9]);
            acc[10] = fmaf(wv.x, f1.y, acc[10]); acc[11] = fmaf(wv.y, f1.y, acc[11]);
            acc[12] = fmaf(wv.x, f1.z, acc[12]); acc[13] = fmaf(wv.y, f1.z, acc[13]);
            acc[14] = fmaf(wv.x, f1.w, acc[14]); acc[15] = fmaf(wv.y, f1.w, acc[15]);
        }
        __syncthreads();   // everyone done reading fsm; reuse as sout[64][65]
        float* som = fsm;
        float b0 = sb[lane], b1 = sb[lane + 32];
#pragma unroll
        for (int j = 0; j < 8; j++) {
            som[lane * 65 + vb + j]        = elu1(acc[2 * j]     + b0);
            som[(lane + 32) * 65 + vb + j] = elu1(acc[2 * j + 1] + b1);
        }
        __syncthreads();
        // ---- write-out: row-major, near-coalesced over clustered queue columns ----
#pragma unroll
        for (int i = tid; i < 64 * 64; i += 256) {
            int o = i >> 6, v = i & 63;
            int nn = s_n[v];
            if (nn >= 0) out[(size_t)o * NVOX + nn] = som[o * 65 + v];
        }
    }
}

extern "C" void kernel_launch(void* const* d_in, const int* in_sizes, int n_in,
                              void* d_out, int out_size) {
    const float* feat = (const float*)d_in[0];
    const float* mask = (const float*)d_in[1];
    const float* K    = (const float*)d_in[2];
    const float* ext  = (const float*)d_in[3];
    const float* w_no = (const float*)d_in[4];
    const float* b_no = (const float*)d_in[5];
    const float* w_o  = (const float*)d_in[6];
    const float* b_o  = (const float*)d_in[7];
    float* out = (float*)d_out;

    static cudaStream_t s1 = nullptr, s2 = nullptr;
    static cudaEvent_t e0 = nullptr, e_t = nullptr, e_p = nullptr, e_c = nullptr,
                       e_g1 = nullptr, e_f = nullptr;
    if (!s1) {
        cudaStreamCreateWithFlags(&s1, cudaStreamNonBlocking);
        cudaStreamCreateWithFlags(&s2, cudaStreamNonBlocking);
        cudaEventCreateWithFlags(&e0,  cudaEventDisableTiming);
        cudaEventCreateWithFlags(&e_t, cudaEventDisableTiming);
        cudaEventCreateWithFlags(&e_p, cudaEventDisableTiming);
        cudaEventCreateWithFlags(&e_c, cudaEventDisableTiming);
        cudaEventCreateWithFlags(&e_g1, cudaEventDisableTiming);
        cudaEventCreateWithFlags(&e_f, cudaEventDisableTiming);
    }

    const int smem1 = (65 * 64  + 65 * 68  + 64 + 64) * 4;   // 34832
    const int smem2 = (130 * 64 + 130 * 68 + 64 + 64) * 4;   // 69152
    cudaFuncSetAttribute(gemm_kernel<65, 0>,  cudaFuncAttributeMaxDynamicSharedMemorySize, smem1);
    cudaFuncSetAttribute(gemm_kernel<130, 1>, cudaFuncAttributeMaxDynamicSharedMemorySize, smem2);

    // fork: transpose on s1, pack on s2, init+classify on capture stream
    cudaEventRecord(e0, 0);
    cudaStreamWaitEvent(s1, e0, 0);
    cudaStreamWaitEvent(s2, e0, 0);

    dim3 tg(HWp / 32, CF / 32, NC);   // 440 x 2 x 6
    transpose_kernel<<<tg, dim3(32, 8), 0, s1>>>(feat);
    cudaEventRecord(e_t, s1);

    pack_kernel<<<17, 256, 0, s2>>>(w_no, w_o);
    cudaEventRecord(e_p, s2);

    init_kernel<<<1, 32>>>();
    classify_kernel<<<(NVOX + 255) / 256, 256>>>(mask, K, ext);
    cudaEventRecord(e_c, 0);

    // big gemm<65> on stream 0: needs transpose + pack (classify in order)
    cudaStreamWaitEvent(0, e_t, 0);
    cudaStreamWaitEvent(0, e_p, 0);
    gemm_kernel<65, 0><<<888, 256, smem1, 0>>>(b_no, out);

    // small gemm<130> on s1: needs classify + pack (transpose in order)
    cudaStreamWaitEvent(s1, e_c, 0);
    cudaStreamWaitEvent(s1, e_p, 0);
    gemm_kernel<130, 1><<<296, 256, smem2, s1>>>(b_o, out);
    cudaEventRecord(e_g1, s1);

    // fill on s2: needs classify only; runs concurrent with gemms
    cudaStreamWaitEvent(s2, e_c, 0);
    fill_kernel<<<(NVOX + 255) / 256, 256, 0, s2>>>(out);
    cudaEventRecord(e_f, s2);

    cudaStreamWaitEvent(0, e_g1, 0);
    cudaStreamWaitEvent(0, e_f, 0);
}